// round 2
// baseline (speedup 1.0000x reference)
#include <cuda_runtime.h>
#include <math.h>

// ---------------- problem constants ----------------
#define BATCH 64
#define TDEC  150
#define NVOC  48
#define LHID  256   // listener hidden per dir
#define SHID  512   // speller hidden
#define NMLP  128

// ---------------- device scratch ----------------
__device__ float g_xw0[64*1024*1024];      // xw fwd  (max 65536 x 1024)
__device__ float g_xw1[64*1024*1024];      // xw bwd
__device__ float g_out0[64*1024*512];
__device__ float g_out1[64*512*512];
__device__ float g_feats[64*256*512];
__device__ float g_cf[64*256*128];         // comp_feat
__device__ float g_h[2*2*64*256];          // [parity][dir][b][256]
__device__ float g_c[2*64*256];            // [dir][b][256]
__device__ float g_dh[2*64*512];           // [parity][b][512]
__device__ float g_ctx[64*512];
__device__ float g_phiWt[512*128];
__device__ unsigned g_bar;                 // grid barrier counter (memset to 0 pre-launch)

// ---------------- software grid barrier ----------------
// Monotonic-counter barrier: counter memset to 0 before each persistent launch.
__device__ __forceinline__ void gbar(unsigned& epoch, unsigned nb)
{
    __syncthreads();
    if (threadIdx.x == 0) {
        __threadfence();
        atomicAdd(&g_bar, 1u);
        unsigned target = epoch + nb;
        volatile unsigned* p = &g_bar;
        while (*p < target) { }
    }
    epoch += nb;
    __syncthreads();
}

// ---------------- fp32 GEMM: C[M,N] = A[M,K] @ W[N,K]^T + bias, opt relu ----
// Tile 128(M) x 64(N), K-step 16, 256 threads, 8x4 per thread.
// Requires M % 128 == 0, N % 64 == 0, K % 16 == 0 (true for all call sites).
__global__ __launch_bounds__(256) void gemm_bias(
    const float* __restrict__ A, const float* __restrict__ W,
    const float* __restrict__ bias, float* __restrict__ C,
    int M, int N, int K, int relu)
{
    __shared__ float As[16 * 132];
    __shared__ float Ws[16 * 68];
    int bm = blockIdx.y << 7, bn = blockIdx.x << 6;
    int tid = threadIdx.x;
    int ty = tid >> 4, tx = tid & 15;
    const float* Ap = A + (size_t)bm * K;
    const float* Wp = W + (size_t)bn * K;

    float acc[8][4];
#pragma unroll
    for (int i = 0; i < 8; i++)
#pragma unroll
        for (int j = 0; j < 4; j++) acc[i][j] = 0.f;

    for (int k0 = 0; k0 < K; k0 += 16) {
#pragma unroll
        for (int j = 0; j < 2; j++) {
            int idx = tid + 256 * j;
            int r = idx >> 2, c = (idx & 3) << 2;
            float4 v = *(const float4*)&Ap[(size_t)r * K + k0 + c];
            As[(c + 0) * 132 + r] = v.x;
            As[(c + 1) * 132 + r] = v.y;
            As[(c + 2) * 132 + r] = v.z;
            As[(c + 3) * 132 + r] = v.w;
        }
        {
            int r = tid >> 2, c = (tid & 3) << 2;
            float4 v = *(const float4*)&Wp[(size_t)r * K + k0 + c];
            Ws[(c + 0) * 68 + r] = v.x;
            Ws[(c + 1) * 68 + r] = v.y;
            Ws[(c + 2) * 68 + r] = v.z;
            Ws[(c + 3) * 68 + r] = v.w;
        }
        __syncthreads();
#pragma unroll
        for (int kk = 0; kk < 16; kk++) {
            float4 a0 = *(const float4*)&As[kk * 132 + ty * 8];
            float4 a1 = *(const float4*)&As[kk * 132 + ty * 8 + 4];
            float4 w  = *(const float4*)&Ws[kk * 68 + tx * 4];
            acc[0][0] += a0.x * w.x; acc[0][1] += a0.x * w.y; acc[0][2] += a0.x * w.z; acc[0][3] += a0.x * w.w;
            acc[1][0] += a0.y * w.x; acc[1][1] += a0.y * w.y; acc[1][2] += a0.y * w.z; acc[1][3] += a0.y * w.w;
            acc[2][0] += a0.z * w.x; acc[2][1] += a0.z * w.y; acc[2][2] += a0.z * w.z; acc[2][3] += a0.z * w.w;
            acc[3][0] += a0.w * w.x; acc[3][1] += a0.w * w.y; acc[3][2] += a0.w * w.z; acc[3][3] += a0.w * w.w;
            acc[4][0] += a1.x * w.x; acc[4][1] += a1.x * w.y; acc[4][2] += a1.x * w.z; acc[4][3] += a1.x * w.w;
            acc[5][0] += a1.y * w.x; acc[5][1] += a1.y * w.y; acc[5][2] += a1.y * w.z; acc[5][3] += a1.y * w.w;
            acc[6][0] += a1.z * w.x; acc[6][1] += a1.z * w.y; acc[6][2] += a1.z * w.z; acc[6][3] += a1.z * w.w;
            acc[7][0] += a1.w * w.x; acc[7][1] += a1.w * w.y; acc[7][2] += a1.w * w.z; acc[7][3] += a1.w * w.w;
        }
        __syncthreads();
    }
    float4 bv = *(const float4*)&bias[bn + tx * 4];
#pragma unroll
    for (int i = 0; i < 8; i++) {
        int m = bm + ty * 8 + i;
        float4 o;
        o.x = acc[i][0] + bv.x; o.y = acc[i][1] + bv.y;
        o.z = acc[i][2] + bv.z; o.w = acc[i][3] + bv.w;
        if (relu) {
            o.x = fmaxf(o.x, 0.f); o.y = fmaxf(o.y, 0.f);
            o.z = fmaxf(o.z, 0.f); o.w = fmaxf(o.w, 0.f);
        }
        *(float4*)&C[(size_t)m * N + bn + tx * 4] = o;
    }
}

// ---------------- persistent encoder scan (both dirs, all timesteps) ----------
// grid (64, 2) = 128 blocks, block 256. Weights stay resident in smem.
// smem: sh_w 16x264, sh_x 64x260  -> 83456 bytes dynamic.
#define ENC_SMEM ((16 * 264 + 64 * 260) * 4)
__global__ __launch_bounds__(256) void enc_scan(
    const float* __restrict__ xw_f, const float* __restrict__ xw_b,
    const float* __restrict__ whh_f, const float* __restrict__ whh_b,
    float* __restrict__ out, int Tl)
{
    extern __shared__ float smem[];
    float* sh_w = smem;               // 16 rows x 256 (pitch 264)
    float* sh_x = smem + 16 * 264;    // 64 rows x 256 (pitch 260)

    int tid = threadIdx.x;
    int lane = tid & 31, wrp = tid >> 5;
    int u = wrp & 3, bh = wrp >> 2;
    int b = bh * 32 + lane;
    int dir = blockIdx.y;
    int hu0 = blockIdx.x << 2;
    int hu = hu0 + u;
    unsigned epoch = 0;
    const unsigned nb = gridDim.x * gridDim.y;

    const float* xw  = dir ? xw_b  : xw_f;
    const float* Whh = dir ? whh_b : whh_f;

    // load Whh tile once: rows (gate g, unit uu) = g*4+uu, 256 cols
    for (int i = tid; i < 16 * 64; i += 256) {
        int r = i >> 6, kq = (i & 63) << 2;
        int grow = ((r >> 2) << 8) + hu0 + (r & 3);
        *(float4*)&sh_w[r * 264 + kq] = *(const float4*)&Whh[(size_t)grow * 256 + kq];
    }

    float creg = 0.f;
    __stcg(&g_h[(size_t)(0 * 2 + dir) * 64 * 256 + b * 256 + hu], 0.f); // parity 0 init
    gbar(epoch, nb);

    for (int t = 0; t < Tl; t++) {
        int tt = dir ? (Tl - 1 - t) : t;
        int pin = t & 1, pout = pin ^ 1;
        const float* hin = g_h + (size_t)(pin * 2 + dir) * 64 * 256;

        __syncthreads();
        for (int i = tid; i < 64 * 64; i += 256) {
            int bb = i >> 6, kq = (i & 63) << 2;
            *(float4*)&sh_x[bb * 260 + kq] = __ldcg((const float4*)&hin[bb * 256 + kq]);
        }
        __syncthreads();

        float acc0 = 0.f, acc1 = 0.f, acc2 = 0.f, acc3 = 0.f;
#pragma unroll 8
        for (int kk = 0; kk < 256; kk += 4) {
            float4 hv = *(const float4*)&sh_x[b * 260 + kk];
            float4 w0 = *(const float4*)&sh_w[(0 * 4 + u) * 264 + kk];
            float4 w1 = *(const float4*)&sh_w[(1 * 4 + u) * 264 + kk];
            float4 w2 = *(const float4*)&sh_w[(2 * 4 + u) * 264 + kk];
            float4 w3 = *(const float4*)&sh_w[(3 * 4 + u) * 264 + kk];
            acc0 += hv.x * w0.x + hv.y * w0.y + hv.z * w0.z + hv.w * w0.w;
            acc1 += hv.x * w1.x + hv.y * w1.y + hv.z * w1.z + hv.w * w1.w;
            acc2 += hv.x * w2.x + hv.y * w2.y + hv.z * w2.z + hv.w * w2.w;
            acc3 += hv.x * w3.x + hv.y * w3.y + hv.z * w3.z + hv.w * w3.w;
        }
        size_t xi = ((size_t)b * Tl + tt) * 1024 + hu;
        float zi = acc0 + xw[xi];
        float zf = acc1 + xw[xi + 256];
        float zg = acc2 + xw[xi + 512];
        float zo = acc3 + xw[xi + 768];
        float si = 1.f / (1.f + expf(-zi));
        float sf = 1.f / (1.f + expf(-zf));
        float so = 1.f / (1.f + expf(-zo));
        float cn = sf * creg + si * tanhf(zg);
        float hn = so * tanhf(cn);
        creg = cn;
        __stcg(&g_h[(size_t)(pout * 2 + dir) * 64 * 256 + b * 256 + hu], hn);
        out[((size_t)b * Tl + tt) * 512 + dir * 256 + hu] = hn;
        gbar(epoch, nb);
    }
    g_c[(size_t)(dir * 64 + b) * 256 + hu] = creg;  // final cell state
}

// ---------------- persistent decoder (LSTM step + attention fused) ------------
// grid 128 blocks x 256. Weights (16 x 1024) resident in smem.
#define DEC_SMEM ((16 * 1032 + 64 * 132 + 512 + 128 + 256 + 512 + 64 + 256) * 4)
__global__ __launch_bounds__(256) void dec_scan(
    const float* __restrict__ sWih, const float* __restrict__ sWhh,
    const float* __restrict__ sb, const int* __restrict__ gt,
    const float* __restrict__ phi_b,
    const float* __restrict__ fcW, const float* __restrict__ fcb,
    float* __restrict__ out_lps)
{
    extern __shared__ float smem[];
    float* sh_w  = smem;                  // 16 x 1024 (pitch 1032)
    float* sh_x  = sh_w + 16 * 1032;      // 64 x 128 (pitch 132)
    float* sh_h  = sh_x + 64 * 132;       // 512
    float* sh_q  = sh_h + 512;            // 128
    float* sh_e  = sh_q + 128;            // 256
    float* sh_c2 = sh_e + 256;            // 512
    float* sh_l  = sh_c2 + 512;           // 64 (48 used)
    float* sr    = sh_l + 64;             // 256

    int tid = threadIdx.x;
    int lane = tid & 31, wrp = tid >> 5;
    int u = wrp & 3, bh = wrp >> 2;
    int b = bh * 32 + lane;
    int hu0 = blockIdx.x << 2;
    int hu = hu0 + u;
    unsigned epoch = 0;
    const unsigned nb = gridDim.x;

    // load weights once: cols 0..511 = Wih[:,48:560], cols 512..1023 = Whh
    for (int i = tid; i < 16 * 256; i += 256) {
        int r = i >> 8, kq = (i & 255) << 2;
        int grow = (r >> 2) * SHID + hu0 + (r & 3);
        float4 v;
        if (kq < 512) v = *(const float4*)&sWih[(size_t)grow * 560 + 48 + kq];
        else          v = *(const float4*)&sWhh[(size_t)grow * 512 + (kq - 512)];
        *(float4*)&sh_w[r * 1032 + kq] = v;
    }

    float creg = 0.f;
    __stcg(&g_dh[(size_t)b * 512 + hu], 0.f);  // parity 0
    __stcg(&g_ctx[(size_t)b * 512 + hu], __ldg(&g_feats[(size_t)b * 256 * 512 + hu]));
    gbar(epoch, nb);

    float bi0 = sb[0 * SHID + hu], bi1 = sb[1 * SHID + hu];
    float bi2 = sb[2 * SHID + hu], bi3 = sb[3 * SHID + hu];

    for (int t = 0; t < TDEC; t++) {
        int pin = t & 1, pout = pin ^ 1;
        int tok = (t == 0) ? 0 : gt[b * TDEC + (t - 1)];
        float acc0 = sWih[(size_t)(0 * SHID + hu) * 560 + tok] + bi0;
        float acc1 = sWih[(size_t)(1 * SHID + hu) * 560 + tok] + bi1;
        float acc2 = sWih[(size_t)(2 * SHID + hu) * 560 + tok] + bi2;
        float acc3 = sWih[(size_t)(3 * SHID + hu) * 560 + tok] + bi3;

        const float* hin = g_dh + (size_t)pin * 64 * 512;
        for (int c = 0; c < 8; c++) {
            __syncthreads();
            const float* src = (c < 4) ? (g_ctx + (c << 7)) : (hin + ((c - 4) << 7));
            for (int i = tid; i < 64 * 32; i += 256) {
                int bb = i >> 5, kq = (i & 31) << 2;
                *(float4*)&sh_x[bb * 132 + kq] = __ldcg((const float4*)&src[(size_t)bb * 512 + kq]);
            }
            __syncthreads();
            const float* wp = sh_w + c * 128;
#pragma unroll 8
            for (int kk = 0; kk < 128; kk += 4) {
                float4 hv = *(const float4*)&sh_x[b * 132 + kk];
                float4 w0 = *(const float4*)&wp[(0 * 4 + u) * 1032 + kk];
                float4 w1 = *(const float4*)&wp[(1 * 4 + u) * 1032 + kk];
                float4 w2 = *(const float4*)&wp[(2 * 4 + u) * 1032 + kk];
                float4 w3 = *(const float4*)&wp[(3 * 4 + u) * 1032 + kk];
                acc0 += hv.x * w0.x + hv.y * w0.y + hv.z * w0.z + hv.w * w0.w;
                acc1 += hv.x * w1.x + hv.y * w1.y + hv.z * w1.z + hv.w * w1.w;
                acc2 += hv.x * w2.x + hv.y * w2.y + hv.z * w2.z + hv.w * w2.w;
                acc3 += hv.x * w3.x + hv.y * w3.y + hv.z * w3.z + hv.w * w3.w;
            }
        }
        float si = 1.f / (1.f + expf(-acc0));
        float sf = 1.f / (1.f + expf(-acc1));
        float so = 1.f / (1.f + expf(-acc3));
        float cn = sf * creg + si * tanhf(acc2);
        float hn = so * tanhf(cn);
        creg = cn;
        __stcg(&g_dh[(size_t)pout * 64 * 512 + b * 512 + hu], hn);
        gbar(epoch, nb);

        // -------- attention / logits: blocks 0..63, one per batch row --------
        if (blockIdx.x < 64) {
            int bb = blockIdx.x;
            const float* h = g_dh + (size_t)pout * 64 * 512 + (size_t)bb * 512;
            for (int i = tid; i < 512; i += 256) sh_h[i] = __ldcg(&h[i]);
            __syncthreads();

            if (tid < 128) {
                float a0 = 0.f, a1 = 0.f, a2 = 0.f, a3 = 0.f;
                for (int k = 0; k < 512; k += 4) {
                    a0 += sh_h[k + 0] * g_phiWt[(k + 0) * 128 + tid];
                    a1 += sh_h[k + 1] * g_phiWt[(k + 1) * 128 + tid];
                    a2 += sh_h[k + 2] * g_phiWt[(k + 2) * 128 + tid];
                    a3 += sh_h[k + 3] * g_phiWt[(k + 3) * 128 + tid];
                }
                float q = a0 + a1 + a2 + a3 + phi_b[tid];
                sh_q[tid] = q > 0.f ? q : 0.f;
            }
            __syncthreads();

            {
                const float* cfp = g_cf + ((size_t)bb * 256 + tid) * 128;
                float a0 = 0.f, a1 = 0.f, a2 = 0.f, a3 = 0.f;
                for (int j = 0; j < 128; j += 4) {
                    a0 += sh_q[j + 0] * cfp[j + 0];
                    a1 += sh_q[j + 1] * cfp[j + 1];
                    a2 += sh_q[j + 2] * cfp[j + 2];
                    a3 += sh_q[j + 3] * cfp[j + 3];
                }
                sh_e[tid] = a0 + a1 + a2 + a3;
            }
            __syncthreads();

            float v = sh_e[tid];
            sr[tid] = v; __syncthreads();
            for (int s = 128; s > 0; s >>= 1) { if (tid < s) sr[tid] = fmaxf(sr[tid], sr[tid + s]); __syncthreads(); }
            float m = sr[0]; __syncthreads();
            float e = expf(v - m);
            sr[tid] = e; __syncthreads();
            for (int s = 128; s > 0; s >>= 1) { if (tid < s) sr[tid] += sr[tid + s]; __syncthreads(); }
            float inv = 1.f / sr[0];
            __syncthreads();
            sh_e[tid] = e * inv;
            __syncthreads();

            for (int d0 = 0; d0 < 512; d0 += 256) {
                int d = d0 + tid;
                const float* fp = g_feats + (size_t)bb * 256 * 512 + d;
                float a0 = 0.f, a1 = 0.f, a2 = 0.f, a3 = 0.f;
                for (int tt2 = 0; tt2 < 256; tt2 += 4) {
                    a0 += sh_e[tt2 + 0] * fp[(size_t)(tt2 + 0) * 512];
                    a1 += sh_e[tt2 + 1] * fp[(size_t)(tt2 + 1) * 512];
                    a2 += sh_e[tt2 + 2] * fp[(size_t)(tt2 + 2) * 512];
                    a3 += sh_e[tt2 + 3] * fp[(size_t)(tt2 + 3) * 512];
                }
                float cv = a0 + a1 + a2 + a3;
                sh_c2[d] = cv;
                __stcg(&g_ctx[(size_t)bb * 512 + d], cv);
            }
            __syncthreads();

            if (tid < 48) {
                const float* wr = fcW + (size_t)tid * 1024;
                float a0 = 0.f, a1 = 0.f;
                for (int k = 0; k < 512; k++) {
                    a0 += sh_h[k] * wr[k];
                    a1 += sh_c2[k] * wr[512 + k];
                }
                sh_l[tid] = a0 + a1 + fcb[tid];
            }
            __syncthreads();
            if (tid < 48) {
                float m2 = -1e30f;
                for (int j = 0; j < 48; j++) m2 = fmaxf(m2, sh_l[j]);
                float s2 = 0.f;
                for (int j = 0; j < 48; j++) s2 += expf(sh_l[j] - m2);
                out_lps[(size_t)bb * TDEC * NVOC + (size_t)t * NVOC + tid] = sh_l[tid] - m2 - logf(s2);
            }
        }
        gbar(epoch, nb);
    }
}

// ---------------- small helpers ----------------
__global__ void transpose_phi(const float* __restrict__ W) { // [128,512] -> [512,128]
    int j = blockIdx.x;
    for (int k = threadIdx.x; k < 512; k += 256) g_phiWt[k * 128 + j] = W[j * 512 + k];
}

__global__ void fin_hc(float* __restrict__ out) { // [B,1024] = [hf|hb|cf|cb]
    int b = blockIdx.x;
    for (int i = threadIdx.x; i < 1024; i += 256) {
        int q = i >> 8, r = i & 255;
        float v;
        if (q == 0)      v = g_h[(size_t)(0 * 2 + 0) * 64 * 256 + b * 256 + r]; // parity 0 (Tl even)
        else if (q == 1) v = g_h[(size_t)(0 * 2 + 1) * 64 * 256 + b * 256 + r];
        else if (q == 2) v = g_c[(size_t)(0 * 64 + b) * 256 + r];
        else             v = g_c[(size_t)(1 * 64 + b) * 256 + r];
        out[(size_t)b * 1024 + i] = v;
    }
}

// ---------------- host launcher ----------------
extern "C" void kernel_launch(void* const* d_in, const int* in_sizes, int n_in,
                              void* d_out, int out_size)
{
    const float* inputs = (const float*)d_in[0];
    const int*   gt     = (const int*)d_in[1];
    const float* W[27];
    for (int i = 0; i < 27; i++) W[i] = (const float*)d_in[i + 2];
    // 0..5 layer0 (f_Wih,f_Whh,f_b,b_Wih,b_Whh,b_b), 6..11 layer1, 12..17 layer2,
    // 18 s_Wih, 19 s_Whh, 20 s_b, 21 phi_W, 22 phi_b, 23 psi_W, 24 psi_b, 25 fc_W, 26 fc_b

    float *xw0, *xw1, *out0, *out1, *feats, *cf;
    unsigned* barp;
    cudaGetSymbolAddress((void**)&xw0, g_xw0);
    cudaGetSymbolAddress((void**)&xw1, g_xw1);
    cudaGetSymbolAddress((void**)&out0, g_out0);
    cudaGetSymbolAddress((void**)&out1, g_out1);
    cudaGetSymbolAddress((void**)&feats, g_feats);
    cudaGetSymbolAddress((void**)&cf, g_cf);
    cudaGetSymbolAddress((void**)&barp, g_bar);

    cudaFuncSetAttribute(enc_scan, cudaFuncAttributeMaxDynamicSharedMemorySize, ENC_SMEM);
    cudaFuncSetAttribute(dec_scan, cudaFuncAttributeMaxDynamicSharedMemorySize, DEC_SMEM);

    float* dout = (float*)d_out;

    // ---------------- encoder ----------------
    const float* A = inputs;
    float* outs[3] = {out0, out1, feats};
    int Tl = 1024, K = 160;
    for (int l = 0; l < 3; l++) {
        int M = 64 * Tl;
        dim3 gg(1024 / 64, M / 128);
        gemm_bias<<<gg, 256>>>(A, W[l * 6 + 0], W[l * 6 + 2], xw0, M, 1024, K, 0);
        gemm_bias<<<gg, 256>>>(A, W[l * 6 + 3], W[l * 6 + 5], xw1, M, 1024, K, 0);
        cudaMemsetAsync(barp, 0, 4);
        enc_scan<<<dim3(64, 2), 256, ENC_SMEM>>>(xw0, xw1, W[l * 6 + 1], W[l * 6 + 4], outs[l], Tl);
        A = outs[l];
        Tl >>= 1;
        K = 1024;
    }

    // comp_feat = relu(feats @ psi_W^T + psi_b)   [16384,128]
    gemm_bias<<<dim3(128 / 64, 16384 / 128), 256>>>(feats, W[23], W[24], cf, 16384, 128, 512, 1);
    transpose_phi<<<128, 256>>>(W[21]);
    fin_hc<<<64, 256>>>(dout + (size_t)BATCH * TDEC * NVOC);

    // ---------------- decoder (single persistent kernel) ----------------
    cudaMemsetAsync(barp, 0, 4);
    dec_scan<<<128, 256, DEC_SMEM>>>(W[18], W[19], W[20], gt, W[22], W[25], W[26], dout);
}